// round 9
// baseline (speedup 1.0000x reference)
#include <cuda_runtime.h>
#include <math.h>

#define NN 50000
#define EE 400000
#define HH 5
#define CC 64
#define HC 320   // H*C
#define ED 16    // edge dim

typedef unsigned long long ull;

// ---------------- scratch (device globals; no allocation allowed) ----------------
__device__ float g_sums[NN * ED];       // self-loop attr (mean of incoming edge attrs)
__device__ int   g_deg[NN];             // in-degree (original edges)
__device__ int   g_rowptr[NN + 1];      // CSR row pointers (by dst)
__device__ int   g_cursor[NN];          // scatter cursors
__device__ int   g_bsum[64];            // block sums for scan
__device__ int2  g_csr[EE];             // (src, eid) per CSR slot
__device__ float g_h[NN * HC];          // per-layer transformed features [N,320]
__device__ float g_act[NN * CC];        // layer activations [N,64]

// ---------------- packed f32x2 helpers ----------------
__device__ __forceinline__ ull pack2(float a) {
    ull r;
    asm("mov.b64 %0,{%1,%1};" : "=l"(r) : "f"(a));
    return r;
}
__device__ __forceinline__ float2 up2(ull v) {
    float2 r;
    asm("mov.b64 {%0,%1},%2;" : "=f"(r.x), "=f"(r.y) : "l"(v));
    return r;
}
__device__ __forceinline__ void ffma2(ull& c, ull a, ull b) {
    asm("fma.rn.f32x2 %0,%1,%2,%0;" : "+l"(c) : "l"(a), "l"(b));
}
__device__ __forceinline__ ull add2(ull a, ull b) {
    ull r;
    asm("add.rn.f32x2 %0,%1,%2;" : "=l"(r) : "l"(a), "l"(b));
    return r;
}

// ---------------- setup kernels ----------------
__global__ void zero_deg_kernel(int N) {
    int i = blockIdx.x * blockDim.x + threadIdx.x;
    if (i < N) g_deg[i] = 0;
}

__global__ void deg_kernel(const int* __restrict__ ei, int E) {
    int e = blockIdx.x * blockDim.x + threadIdx.x;
    if (e >= E) return;
    atomicAdd(&g_deg[ei[E + e]], 1);
}

// phase A: per-1024 block scan, local exclusive into rowptr, block totals into g_bsum
__global__ void scan_a_kernel(int N) {
    __shared__ int sw[32];
    int t = threadIdx.x, lane = t & 31, wid = t >> 5;
    int i = blockIdx.x * 1024 + t;
    int v = (i < N) ? g_deg[i] : 0;
    int incl = v;
#pragma unroll
    for (int o = 1; o < 32; o <<= 1) {
        int u = __shfl_up_sync(0xffffffffu, incl, o);
        if (lane >= o) incl += u;
    }
    if (lane == 31) sw[wid] = incl;
    __syncthreads();
    if (t < 32) {
        int w = sw[t], s = w;
#pragma unroll
        for (int o = 1; o < 32; o <<= 1) {
            int u = __shfl_up_sync(0xffffffffu, s, o);
            if (t >= o) s += u;
        }
        sw[t] = s - w;
    }
    __syncthreads();
    int excl = sw[wid] + incl - v;
    if (i < N) g_rowptr[i] = excl;
    if (t == 1023) g_bsum[blockIdx.x] = excl + v;
}

// phase B: exclusive scan of block sums (nb <= 64), one block of 64 threads
__global__ void scan_b_kernel(int nb) {
    __shared__ int w0;
    int t = threadIdx.x;
    int v = (t < nb) ? g_bsum[t] : 0;
    int incl = v;
#pragma unroll
    for (int o = 1; o < 32; o <<= 1) {
        int u = __shfl_up_sync(0xffffffffu, incl, o);
        if ((t & 31) >= o) incl += u;
    }
    if (t == 31) w0 = incl;
    __syncthreads();
    int excl = incl - v + ((t >= 32) ? w0 : 0);
    g_bsum[t] = excl;
}

// phase C: add block offsets, init cursors, set rowptr[N]
__global__ void scan_c_kernel(int N, int E) {
    int i = blockIdx.x * blockDim.x + threadIdx.x;
    if (i < N) {
        int r = g_rowptr[i] + g_bsum[i >> 10];
        g_rowptr[i] = r;
        g_cursor[i] = r;
    }
    if (i == 0) g_rowptr[N] = E;
}

__global__ void scatter_kernel(const int* __restrict__ ei, int E) {
    int e = blockIdx.x * blockDim.x + threadIdx.x;
    if (e >= E) return;
    int s = ei[e];
    int d = ei[E + e];
    int pos = atomicAdd(&g_cursor[d], 1);
    g_csr[pos] = make_int2(s, e);
}

// self-loop attrs: mean of incoming edge attrs per node (atomic-free, CSR gather)
__global__ void __launch_bounds__(256) sums_kernel(const float* __restrict__ ea, int N) {
    int t = threadIdx.x;
    int n = blockIdx.x * 16 + (t >> 4);
    int c = t & 15;
    if (n >= N) return;
    int beg = g_rowptr[n], end = g_rowptr[n + 1];
    float s = 0.0f;
    for (int j = beg; j < end; j++) {
        int eid = g_csr[j].y;
        s += ea[(size_t)eid * ED + c];
    }
    int d = end - beg;
    if (d < 1) d = 1;
    g_sums[(size_t)n * ED + c] = s / (float)d;
}

// ---------------- GEMM: g_h[N,320] = A[N,K] @ W[K,320] + b  (f32x2 MACs) ----------------
template <int K, bool USE_ACT>
__global__ void __launch_bounds__(256) gemm_kernel(const float* __restrict__ Ain,
                                                   const float* __restrict__ W,
                                                   const float* __restrict__ b, int N) {
    const float* A = USE_ACT ? (const float*)g_act : Ain;
    __shared__ float As[16][64];
    __shared__ float Ws[16][HC];
    int tid = threadIdx.x;
    int cg = tid & 31;   // lane: column pairs (2cg + 64i, +1), i<5
    int rg = tid >> 5;   // warp: rows rg*8 .. rg*8+7 within 64-row block
    int row0 = blockIdx.x * 64;

    ull acc2[8][5];
#pragma unroll
    for (int r = 0; r < 8; r++)
#pragma unroll
        for (int i = 0; i < 5; i++) acc2[r][i] = 0ull;

    for (int kc = 0; kc < K; kc += 16) {
        {   // stage A chunk (transposed): As[k][r] = A[row0+r][kc+k]
            int r = tid >> 2;
            int kk = (tid & 3) * 4;
            int row = row0 + r;
            float4 v = make_float4(0.f, 0.f, 0.f, 0.f);
            if (row < N) v = *(const float4*)(A + (size_t)row * K + kc + kk);
            As[kk + 0][r] = v.x;
            As[kk + 1][r] = v.y;
            As[kk + 2][r] = v.z;
            As[kk + 3][r] = v.w;
        }
        {   // stage W chunk: 16 x 320 = 1280 float4
            const float4* Wv = (const float4*)(W + (size_t)kc * HC);
            float4* Wsv = (float4*)&Ws[0][0];
#pragma unroll
            for (int i = 0; i < 5; i++) Wsv[i * 256 + tid] = Wv[i * 256 + tid];
        }
        __syncthreads();
#pragma unroll
        for (int k = 0; k < 16; k++) {
            float4 a0 = *(const float4*)&As[k][rg * 8];
            float4 a1 = *(const float4*)&As[k][rg * 8 + 4];
            ull a2[8] = {pack2(a0.x), pack2(a0.y), pack2(a0.z), pack2(a0.w),
                         pack2(a1.x), pack2(a1.y), pack2(a1.z), pack2(a1.w)};
            ull w2[5];
#pragma unroll
            for (int i = 0; i < 5; i++) w2[i] = *(const ull*)&Ws[k][2 * cg + 64 * i];
#pragma unroll
            for (int r = 0; r < 8; r++)
#pragma unroll
                for (int i = 0; i < 5; i++) ffma2(acc2[r][i], a2[r], w2[i]);
        }
        __syncthreads();
    }
    float2 bb[5];
#pragma unroll
    for (int i = 0; i < 5; i++) bb[i] = *(const float2*)(b + 2 * cg + 64 * i);
#pragma unroll
    for (int r = 0; r < 8; r++) {
        int row = row0 + rg * 8 + r;
        if (row < N) {
            float* hp = g_h + (size_t)row * HC + 2 * cg;
#pragma unroll
            for (int i = 0; i < 5; i++) {
                float2 v = up2(acc2[r][i]);
                v.x += bb[i].x;
                v.y += bb[i].y;
                *(float2*)(hp + 64 * i) = v;
            }
        }
    }
}

// ---------------- attention: warp/dst, pair-unrolled, software-pipelined ----------------
struct PairBuf {
    int sA, sB;        // src nodes
    int eA, eB;        // edge ids
    ull hsA[5], hsB[5];
    float4 qA0, qA1, qB0, qB1;  // first half of edge attrs
};

__device__ __forceinline__ void pf(PairBuf& b, int j, int end, int l,
                                   const float* __restrict__ ea) {
    int jA = j, jB = j + 1;
    if (jB >= end) jB = jA;
    int2 cA = __ldg(&g_csr[jA]);
    int2 cB = __ldg(&g_csr[jB]);
    b.sA = cA.x;
    b.sB = cB.x;
    b.eA = cA.y;
    b.eB = cB.y;
    const float* hA = g_h + (size_t)cA.x * HC + 2 * l;
    const float* hB = g_h + (size_t)cB.x * HC + 2 * l;
#pragma unroll
    for (int h = 0; h < HH; h++) {
        b.hsA[h] = *(const ull*)(hA + h * CC);
        b.hsB[h] = *(const ull*)(hB + h * CC);
    }
    const float4* pA = (const float4*)(ea + (size_t)cA.y * ED);
    const float4* pB = (const float4*)(ea + (size_t)cB.y * ED);
    b.qA0 = pA[0];
    b.qA1 = pA[1];
    b.qB0 = pB[0];
    b.qB1 = pB[1];
}

__device__ __forceinline__ void quad_step(ull ev[5], const float4& q, const float* wb) {
    float av[4] = {q.x, q.y, q.z, q.w};
#pragma unroll
    for (int s = 0; s < 4; s++) {
        ull a2 = pack2(av[s]);
#pragma unroll
        for (int h = 0; h < HH; h++) {
            ull w = *(const ull*)(wb + h * CC);
            ffma2(ev[h], a2, w);
        }
        wb += HC;
    }
}

__device__ __forceinline__ void edge_finish(const ull ev[5], const ull hs[5],
                                            const float2 at2[5], float d5[5], float2 acc[5]) {
    float p5[5];
#pragma unroll
    for (int h = 0; h < HH; h++) {
        float2 v = up2(ev[h]);
        float lx = fmaf(0.2f, fminf(v.x, 0.f), fmaxf(v.x, 0.f));
        float ly = fmaf(0.2f, fminf(v.y, 0.f), fmaxf(v.y, 0.f));
        p5[h] = fmaf(lx, at2[h].x, ly * at2[h].y);
    }
#pragma unroll
    for (int o = 16; o > 0; o >>= 1)
#pragma unroll
        for (int h = 0; h < HH; h++) p5[h] += __shfl_xor_sync(0xffffffffu, p5[h], o);
#pragma unroll
    for (int h = 0; h < HH; h++) {
        float pe = __expf(fminf(p5[h], 80.0f));
        float2 hv = up2(hs[h]);
        d5[h] += pe;
        acc[h].x = fmaf(pe, hv.x, acc[h].x);
        acc[h].y = fmaf(pe, hv.y, acc[h].y);
    }
}

__device__ __forceinline__ void compute_pair(const PairBuf& b, bool two, int l,
                                             const float* __restrict__ ea,
                                             const float* __restrict__ We_s, const ull hdp[5],
                                             const float2 at2[5], float d5[5], float2 acc[5]) {
    // issue second-half edge-attr loads early (uniform address, L1/L2)
    const float4* pA = (const float4*)(ea + (size_t)b.eA * ED);
    const float4* pB = (const float4*)(ea + (size_t)b.eB * ED);
    float4 qA2 = pA[2], qA3 = pA[3], qB2 = pB[2], qB3 = pB[3];

    ull evA[5], evB[5];
#pragma unroll
    for (int h = 0; h < HH; h++) {
        evA[h] = add2(b.hsA[h], hdp[h]);
        evB[h] = add2(b.hsB[h], hdp[h]);
    }
    const float* wb = We_s + 2 * l;
    quad_step(evA, b.qA0, wb);
    quad_step(evB, b.qB0, wb);
    quad_step(evA, b.qA1, wb + 4 * HC);
    quad_step(evB, b.qB1, wb + 4 * HC);
    quad_step(evA, qA2, wb + 8 * HC);
    quad_step(evB, qB2, wb + 8 * HC);
    quad_step(evA, qA3, wb + 12 * HC);
    quad_step(evB, qB3, wb + 12 * HC);

    edge_finish(evA, b.hsA, at2, d5, acc);
    if (two) edge_finish(evB, b.hsB, at2, d5, acc);
}

__global__ void __launch_bounds__(128, 3) attn_kernel(const float* __restrict__ edge_attr,
                                                      const float* __restrict__ We,
                                                      const float* __restrict__ att,
                                                      const float* __restrict__ bias,
                                                      float* __restrict__ outp, int N,
                                                      int use_act_out) {
    __shared__ float We_s[ED * HC];  // 20KB
    {
        const float4* s4 = (const float4*)We;
        float4* d4 = (float4*)We_s;
        for (int i = threadIdx.x; i < (ED * HC) / 4; i += 128) d4[i] = s4[i];
    }
    __syncthreads();

    int l = threadIdx.x & 31;
    int n = blockIdx.x * 4 + (threadIdx.x >> 5);
    if (n >= N) return;

    ull hdp[5];
    float2 at2[5];
    const float* hrd = g_h + (size_t)n * HC + 2 * l;
#pragma unroll
    for (int h = 0; h < HH; h++) {
        hdp[h] = *(const ull*)(hrd + h * CC);
        at2[h] = *(const float2*)(att + h * CC + 2 * l);
    }
    float d5[5];
    float2 acc[5];
#pragma unroll
    for (int h = 0; h < HH; h++) {
        d5[h] = 0.0f;
        acc[h] = make_float2(0.0f, 0.0f);
    }
    const float* wb = We_s + 2 * l;
    int beg = g_rowptr[n], end = g_rowptr[n + 1];

    // prefetch first pair before self-loop compute (overlap L2 latency)
    PairBuf b0, b1;
    if (beg < end) pf(b0, beg, end, l, edge_attr);

    // ---- self loop: v = 2*hd + e(loop_attr) ----
    {
        ull ev[5];
#pragma unroll
        for (int h = 0; h < HH; h++) ev[h] = add2(hdp[h], hdp[h]);
        const float4* sp = (const float4*)(g_sums + (size_t)n * ED);
#pragma unroll
        for (int q = 0; q < 4; q++) quad_step(ev, sp[q], wb + q * 4 * HC);
        edge_finish(ev, hdp, at2, d5, acc);
    }

    // ---- incoming edges: ping-pong pipelined pairs ----
    int j = beg;
    if (j < end) {
        while (true) {
            int jn = j + 2;
            bool hn = jn < end;
            if (hn) pf(b1, jn, end, l, edge_attr);
            compute_pair(b0, j + 1 < end, l, edge_attr, We_s, hdp, at2, d5, acc);
            if (!hn) break;
            j = jn;
            jn = j + 2;
            bool hn2 = jn < end;
            if (hn2) pf(b0, jn, end, l, edge_attr);
            compute_pair(b1, j + 1 < end, l, edge_attr, We_s, hdp, at2, d5, acc);
            if (!hn2) break;
            j = jn;
        }
    }

    // ---- epilogue: head mean + bias + ELU ----
    float ox = 0.0f, oy = 0.0f;
#pragma unroll
    for (int h = 0; h < HH; h++) {
        float inv = __fdividef(1.0f, d5[h]);
        ox = fmaf(acc[h].x, inv, ox);
        oy = fmaf(acc[h].y, inv, oy);
    }
    ox *= 0.2f;  // 1/H
    oy *= 0.2f;
    float2 bv = *(const float2*)(bias + 2 * l);
    ox += bv.x;
    oy += bv.y;
    ox = (ox > 0.0f) ? ox : expm1f(ox);
    oy = (oy > 0.0f) ? oy : expm1f(oy);
    float* dst = use_act_out ? (g_act + (size_t)n * CC) : (outp + (size_t)n * CC);
    *(float2*)(dst + 2 * l) = make_float2(ox, oy);
}

// ---------------- launch ----------------
extern "C" void kernel_launch(void* const* d_in, const int* in_sizes, int n_in, void* d_out,
                              int out_size) {
    const float* x     = (const float*)d_in[0];
    const int*   ei    = (const int*)d_in[1];
    const float* ea    = (const float*)d_in[2];
    const float* W0    = (const float*)d_in[3];
    const float* b0    = (const float*)d_in[4];
    const float* We0   = (const float*)d_in[5];
    const float* att0  = (const float*)d_in[6];
    const float* bi0   = (const float*)d_in[7];
    const float* W12   = (const float*)d_in[8];
    const float* b12   = (const float*)d_in[9];
    const float* We12  = (const float*)d_in[10];
    const float* att12 = (const float*)d_in[11];
    const float* bi12  = (const float*)d_in[12];
    float* out = (float*)d_out;

    int N = in_sizes[0] / 128;
    int E = in_sizes[1] / 2;
    int nb = (N + 1023) / 1024;

    // setup: degrees -> parallel scan -> CSR scatter -> self-loop mean attrs
    zero_deg_kernel<<<(N + 255) / 256, 256>>>(N);
    deg_kernel<<<(E + 255) / 256, 256>>>(ei, E);
    scan_a_kernel<<<nb, 1024>>>(N);
    scan_b_kernel<<<1, 64>>>(nb);
    scan_c_kernel<<<(N + 255) / 256, 256>>>(N, E);
    scatter_kernel<<<(E + 255) / 256, 256>>>(ei, E);
    sums_kernel<<<(N + 15) / 16, 256>>>(ea, N);

    int gb = (N + 63) / 64;
    int ab = (N + 3) / 4;

    // layer 0
    gemm_kernel<128, false><<<gb, 256>>>(x, W0, b0, N);
    attn_kernel<<<ab, 128>>>(ea, We0, att0, bi0, nullptr, N, 1);
    // layer 1
    gemm_kernel<64, true><<<gb, 256>>>(nullptr, W12, b12, N);
    attn_kernel<<<ab, 128>>>(ea, We12, att12, bi12, nullptr, N, 1);
    // layer 2
    gemm_kernel<64, true><<<gb, 256>>>(nullptr, W12 + 64 * HC, b12 + HC, N);
    attn_kernel<<<ab, 128>>>(ea, We12 + ED * HC, att12 + HH * CC, bi12 + CC, out, N, 0);
}